// round 5
// baseline (speedup 1.0000x reference)
#include <cuda_runtime.h>
#include <cuda_bf16.h>
#include <cstdint>

#define N_PROD 100000
#define N_CUST 50000
#define HID    128
#define DOUT   64
#define E_PP   800000
#define E_PC   800000
#define E_LB   400000

typedef unsigned long long u64;
typedef __nv_bfloat16 bf16;

#define SWZ(x) ((x) ^ (((x) >> 3) & 0x70))

__device__ __forceinline__ uint32_t smem_u32(const void* p) {
    uint32_t a;
    asm("{ .reg .u64 t; cvta.to.shared.u64 t, %1; cvt.u32.u64 %0, t; }" : "=r"(a) : "l"(p));
    return a;
}
__device__ __forceinline__ void cp16(uint32_t dst, const void* src, int sz) {
    asm volatile("cp.async.cg.shared.global [%0],[%1],16,%2;"
                 :: "r"(dst), "l"(src), "r"(sz));
}
#define CP_WAIT() asm volatile("cp.async.wait_all;" ::: "memory")

__device__ __forceinline__ void ldm4(uint32_t addr, uint32_t* r) {
    asm volatile("ldmatrix.sync.aligned.m8n8.x4.shared.b16 {%0,%1,%2,%3},[%4];"
                 : "=r"(r[0]), "=r"(r[1]), "=r"(r[2]), "=r"(r[3]) : "r"(addr));
}
__device__ __forceinline__ void mma16816(float* d, const uint32_t* a,
                                         uint32_t b0, uint32_t b1) {
    asm volatile(
        "mma.sync.aligned.m16n8k16.row.col.f32.bf16.bf16.f32 "
        "{%0,%1,%2,%3},{%4,%5,%6,%7},{%8,%9},{%0,%1,%2,%3};"
        : "+f"(d[0]), "+f"(d[1]), "+f"(d[2]), "+f"(d[3])
        : "r"(a[0]), "r"(a[1]), "r"(a[2]), "r"(a[3]), "r"(b0), "r"(b1));
}
__device__ __forceinline__ void split1(float w, unsigned short& h, unsigned short& l) {
    bf16 hb = __float2bfloat16_rn(w);
    bf16 lb = __float2bfloat16_rn(w - __bfloat162float(hb));
    h = __bfloat16_as_ushort(hb);
    l = __bfloat16_as_ushort(lb);
}
// f32x2 helpers (decoder)
__device__ __forceinline__ u64 pack2(float lo, float hi) {
    u64 r; asm("mov.b64 %0,{%1,%2};" : "=l"(r) : "f"(lo), "f"(hi)); return r;
}
__device__ __forceinline__ u64 dup2(float a) {
    u64 r; asm("mov.b64 %0,{%1,%1};" : "=l"(r) : "f"(a)); return r;
}
__device__ __forceinline__ void fma2(u64& d, u64 a, u64 b) {
    asm("fma.rn.f32x2 %0,%1,%2,%0;" : "+l"(d) : "l"(a), "l"(b));
}
__device__ __forceinline__ void unpack2(u64 v, float& lo, float& hi) {
    asm("mov.b64 {%0,%1},%2;" : "=f"(lo), "=f"(hi) : "l"(v));
}

// ---------------------------------------------------------------------------
// Scratch: bf16 hi/lo planes for all GEMM activation operands
// ---------------------------------------------------------------------------
__device__ bf16 g_xPH[(size_t)N_PROD * HID];
__device__ bf16 g_xPL[(size_t)N_PROD * HID];
__device__ bf16 g_xCH[(size_t)N_CUST * HID];
__device__ bf16 g_xCL[(size_t)N_CUST * HID];
__device__ bf16 g_P0H[(size_t)N_PROD * HID];
__device__ bf16 g_P0L[(size_t)N_PROD * HID];
__device__ bf16 g_P1H[(size_t)N_PROD * HID];
__device__ bf16 g_P1L[(size_t)N_PROD * HID];
__device__ bf16 g_P2H[(size_t)N_PROD * HID];
__device__ bf16 g_P2L[(size_t)N_PROD * HID];
__device__ bf16 g_P3H[(size_t)N_PROD * HID];
__device__ bf16 g_P3L[(size_t)N_PROD * HID];
__device__ bf16 g_C0H[(size_t)N_CUST * HID];
__device__ bf16 g_C0L[(size_t)N_CUST * HID];
__device__ bf16 g_C1H[(size_t)N_CUST * HID];
__device__ bf16 g_C1L[(size_t)N_CUST * HID];
__device__ bf16 g_C2H[(size_t)N_CUST * HID];
__device__ bf16 g_C2L[(size_t)N_CUST * HID];
__device__ float g_zprod[(size_t)N_PROD * DOUT];
__device__ float g_zcust[(size_t)N_CUST * DOUT];

__device__ int g_cntP[N_PROD];
__device__ int g_cntC[N_CUST];
__device__ int g_offP[N_PROD];
__device__ int g_curP[N_PROD];
__device__ int g_csrP[E_PP];
__device__ int g_offC[N_CUST];
__device__ int g_curC[N_CUST];
__device__ int g_csrC[E_PC];
__device__ u64 g_lbP[128];
__device__ u64 g_lbC[64];

// ---------------------------------------------------------------------------
// CSR: count -> lookback scan (1 kernel) -> fill ; zeroing done by tail kernel
// ---------------------------------------------------------------------------
__global__ void k_count(const int* __restrict__ dst, int E, int* __restrict__ cnt) {
    int e = blockIdx.x * blockDim.x + threadIdx.x;
    if (e < E) atomicAdd(&cnt[dst[e]], 1);
}

__global__ void k_scan_lb(const int* __restrict__ cnt, int n,
                          int* __restrict__ off, int* __restrict__ cur,
                          u64* __restrict__ st) {
    __shared__ int s[1024];
    __shared__ int s_prefix;
    int bid = blockIdx.x, tx = threadIdx.x;
    int gid = bid * 1024 + tx;
    int v = (gid < n) ? cnt[gid] : 0;
    s[tx] = v;
    __syncthreads();
#pragma unroll
    for (int d = 1; d < 1024; d <<= 1) {
        int t = (tx >= d) ? s[tx - d] : 0;
        __syncthreads();
        s[tx] += t;
        __syncthreads();
    }
    int incl = s[tx];
    int total = s[1023];
    if (tx == 0) {
        if (bid == 0) {
            s_prefix = 0;
            atomicExch(st, ((u64)(unsigned)total << 32) | 2ULL);
        } else {
            atomicExch(st + bid, ((u64)(unsigned)total << 32) | 1ULL);
            int run = 0, j = bid - 1;
            while (true) {
                u64 x;
                do { x = atomicAdd(st + j, 0ULL); } while ((x & 3ULL) == 0ULL);
                run += (int)(unsigned)(x >> 32);
                if ((x & 3ULL) == 2ULL) break;
                j--;
            }
            s_prefix = run;
            atomicExch(st + bid, ((u64)(unsigned)(run + total) << 32) | 2ULL);
        }
    }
    __syncthreads();
    if (gid < n) {
        int e = s_prefix + incl - v;
        off[gid] = e;
        cur[gid] = e;
    }
}

__global__ void k_fill(const int* __restrict__ src, const int* __restrict__ dst, int E,
                       int* __restrict__ cur, int* __restrict__ csr) {
    int e = blockIdx.x * blockDim.x + threadIdx.x;
    if (e < E) {
        int d = dst[e];
        int p = atomicAdd(&cur[d], 1);
        csr[p] = src[e];
    }
}

// Tail: restore the zero invariant for next call
__global__ void k_tail_zero() {
    int i = blockIdx.x * blockDim.x + threadIdx.x;
    if (i < N_PROD) g_cntP[i] = 0;
    if (i < N_CUST) g_cntC[i] = 0;
    if (i < 128) g_lbP[i] = 0;
    if (i < 64) g_lbC[i] = 0;
}

// ---------------------------------------------------------------------------
// One-time convert: fp32 x -> bf16 hi/lo planes (prod then cust)
// ---------------------------------------------------------------------------
__global__ void k_convert_x(const float* __restrict__ xp, const float* __restrict__ xc) {
    int i = blockIdx.x * blockDim.x + threadIdx.x;   // one per 4 elems
    const int NP4 = N_PROD * HID / 4;
    const int NC4 = N_CUST * HID / 4;
    const float* src;
    bf16 *dh, *dl;
    int o;
    if (i < NP4) { src = xp; dh = g_xPH; dl = g_xPL; o = i; }
    else if (i < NP4 + NC4) { src = xc; dh = g_xCH; dl = g_xCL; o = i - NP4; }
    else return;
    float4 v = *reinterpret_cast<const float4*>(src + (size_t)o * 4);
    unsigned short h0, l0, h1, l1, h2, l2, h3, l3;
    split1(v.x, h0, l0); split1(v.y, h1, l1);
    split1(v.z, h2, l2); split1(v.w, h3, l3);
    u64 hp = (u64)h0 | ((u64)h1 << 16) | ((u64)h2 << 32) | ((u64)h3 << 48);
    u64 lp = (u64)l0 | ((u64)l1 << 16) | ((u64)l2 << 32) | ((u64)l3 << 48);
    *reinterpret_cast<u64*>(dh + (size_t)o * 4) = hp;
    *reinterpret_cast<u64*>(dl + (size_t)o * 4) = lp;
}

// ---------------------------------------------------------------------------
// Mean aggregation: fp32-in or plane-in; plane output (hi/lo)
// ---------------------------------------------------------------------------
template <bool IN_PLANES>
__global__ void agg_mean(const float* __restrict__ xf,
                         const bf16* __restrict__ xh, const bf16* __restrict__ xl,
                         const int* __restrict__ off, const int* __restrict__ csr,
                         bf16* __restrict__ oh, bf16* __restrict__ ol,
                         int n, int E) {
    int w = (blockIdx.x * blockDim.x + threadIdx.x) >> 5;
    int lane = threadIdx.x & 31;
    if (w >= n) return;
    int beg = off[w];
    int end = (w + 1 < n) ? off[w + 1] : E;
    float a0 = 0.f, a1 = 0.f, a2 = 0.f, a3 = 0.f;
    for (int j = beg; j < end; j++) {
        int s0 = csr[j];
        if (IN_PLANES) {
            u64 hp = __ldg(reinterpret_cast<const u64*>(xh + (size_t)s0 * HID + lane * 4));
            u64 lp = __ldg(reinterpret_cast<const u64*>(xl + (size_t)s0 * HID + lane * 4));
            ushort4 hu = *reinterpret_cast<ushort4*>(&hp);
            ushort4 lu = *reinterpret_cast<ushort4*>(&lp);
            a0 += __bfloat162float(__ushort_as_bfloat16(hu.x)) + __bfloat162float(__ushort_as_bfloat16(lu.x));
            a1 += __bfloat162float(__ushort_as_bfloat16(hu.y)) + __bfloat162float(__ushort_as_bfloat16(lu.y));
            a2 += __bfloat162float(__ushort_as_bfloat16(hu.z)) + __bfloat162float(__ushort_as_bfloat16(lu.z));
            a3 += __bfloat162float(__ushort_as_bfloat16(hu.w)) + __bfloat162float(__ushort_as_bfloat16(lu.w));
        } else {
            float4 v = __ldg(reinterpret_cast<const float4*>(xf + (size_t)s0 * HID + lane * 4));
            a0 += v.x; a1 += v.y; a2 += v.z; a3 += v.w;
        }
    }
    float sc = (end > beg) ? 1.0f / (float)(end - beg) : 0.f;
    a0 *= sc; a1 *= sc; a2 *= sc; a3 *= sc;
    unsigned short h0, l0, h1, l1, h2, l2, h3, l3;
    split1(a0, h0, l0); split1(a1, h1, l1); split1(a2, h2, l2); split1(a3, h3, l3);
    u64 hp = (u64)h0 | ((u64)h1 << 16) | ((u64)h2 << 32) | ((u64)h3 << 48);
    u64 lp = (u64)l0 | ((u64)l1 << 16) | ((u64)l2 << 32) | ((u64)l3 << 48);
    *reinterpret_cast<u64*>(oh + (size_t)w * HID + lane * 4) = hp;
    *reinterpret_cast<u64*>(ol + (size_t)w * HID + lane * 4) = lp;
}

// ---------------------------------------------------------------------------
// HMMA bf16x3 GEMM — pre-split plane operands, cp.async staging
//   DUAL:  out = act([A|X] @ [Wl;Wr]^T + b)  K_TOT=256, N_OUT=128, MTILE=256
//   else:  out = A @ Wl^T + b                K_TOT=128, N_OUT=64,  MTILE=512
// OUT_PLANES: write bf16 hi/lo planes; else fp32.
// ---------------------------------------------------------------------------
template <int N_OUT, int K_TOT, bool DUAL, bool RELU, bool OUT_PLANES>
__global__ __launch_bounds__(512, 1) void hmma_gemm(
    const bf16* __restrict__ AH, const bf16* __restrict__ AL,
    const bf16* __restrict__ XH, const bf16* __restrict__ XL,
    const float* __restrict__ Wl, const float* __restrict__ Wr,
    const float* __restrict__ bias,
    float* __restrict__ outF, bf16* __restrict__ outH, bf16* __restrict__ outL,
    int n)
{
    constexpr int KSTEPS = K_TOT / 16;
    constexpr int NF2    = (N_OUT / 8) / 2;
    constexpr int MTILE  = (N_OUT == 128) ? 256 : 512;
    constexpr int ASPLIT = MTILE * 128;                 // bytes per split plane
    constexpr int BOFF   = 1024 + 2 * ASPLIT;
    constexpr int BSPLIT = KSTEPS * NF2 * 32 * 16;
    constexpr int NCHUNK = K_TOT / 64;
    constexpr int CPTOT  = MTILE * 8 * 2;               // cp.async per chunk

    extern __shared__ char smem[];
    const uint32_t sb = smem_u32(smem);
    const int tid = threadIdx.x;
    const int w = tid >> 5, lane = tid & 31;
    const int g     = (N_OUT == 128) ? (w & 1) : 0;
    const int warpM = (N_OUT == 128) ? (w >> 1) * 32 : w * 32;

    float* bs = (float*)smem;
    if (tid < N_OUT) bs[tid] = bias[tid];

    // W preload in fragment order (hi then lo), once per CTA
    for (int idx = tid; idx < 2 * KSTEPS * NF2 * 32; idx += 512) {
        int l = idx & 31;
        int rest = idx >> 5;
        int nfp = rest % NF2;
        int rest2 = rest / NF2;
        int ks = rest2 % KSTEPS;
        int s = rest2 / KSTEPS;
        uint32_t vals[4];
#pragma unroll
        for (int e = 0; e < 2; e++) {
            int nf = nfp * 2 + e;
            int nn = nf * 8 + (l >> 2);
            int k0 = ks * 16 + (l & 3) * 2;
            const float* wp = Wl;
            int kk = k0;
            if (DUAL && k0 >= 128) { wp = Wr; kk = k0 - 128; }
            float2 wa = *reinterpret_cast<const float2*>(wp + nn * 128 + kk);
            float2 wb = *reinterpret_cast<const float2*>(wp + nn * 128 + kk + 8);
            unsigned short h, lo, r00, r01, r10, r11;
            split1(wa.x, h, lo); r00 = s ? lo : h;
            split1(wa.y, h, lo); r01 = s ? lo : h;
            split1(wb.x, h, lo); r10 = s ? lo : h;
            split1(wb.y, h, lo); r11 = s ? lo : h;
            vals[e * 2 + 0] = (uint32_t)r00 | ((uint32_t)r01 << 16);
            vals[e * 2 + 1] = (uint32_t)r10 | ((uint32_t)r11 << 16);
        }
        *reinterpret_cast<uint4*>(smem + BOFF + (size_t)idx * 16) =
            make_uint4(vals[0], vals[1], vals[2], vals[3]);
    }
    __syncthreads();

    const int ntiles = (n + MTILE - 1) / MTILE;

    for (int tt = blockIdx.x; tt < ntiles; tt += gridDim.x) {
        float acc[2][8][4];
#pragma unroll
        for (int t = 0; t < 2; t++)
#pragma unroll
            for (int nf = 0; nf < 8; nf++)
#pragma unroll
                for (int q = 0; q < 4; q++) acc[t][nf][q] = 0.f;

        for (int chunk = 0; chunk < NCHUNK; chunk++) {
            __syncthreads();
            // stage A chunk: cp.async 16B copies from planes into swizzled SMEM
            {
                const bf16* sh = (DUAL && chunk >= 2) ? XH : AH;
                const bf16* sl = (DUAL && chunk >= 2) ? XL : AL;
                const int colbase = (chunk & 1) * 64;
#pragma unroll
                for (int it = 0; it < CPTOT / 512; it++) {
                    int u = tid + it * 512;
                    int plane = u >= CPTOT / 2;
                    int v = plane ? (u - CPTOT / 2) : u;
                    int r0 = v >> 3;
                    int ch = v & 7;
                    const bf16* src = plane ? sl : sh;
                    int gr = tt * MTILE + r0;
                    uint32_t dst = sb + 1024 + plane * ASPLIT +
                                   SWZ((uint32_t)(r0 * 128 + ch * 16));
                    const void* gp = src + (size_t)gr * 128 + colbase + ch * 8;
                    cp16(dst, gp, (gr < n) ? 16 : 0);
                }
            }
            CP_WAIT();
            __syncthreads();

#pragma unroll
            for (int ksl = 0; ksl < 4; ksl++) {
                const int ks = chunk * 4 + ksl;
                uint32_t ah[2][4], al[2][4];
#pragma unroll
                for (int t = 0; t < 2; t++) {
                    int arow = warpM + (lane & 15) + t * 16;
                    int colb = ksl * 32 + ((lane >> 4) << 4);
                    uint32_t off = SWZ((uint32_t)(arow * 128 + colb));
                    ldm4(sb + 1024 + off, ah[t]);
                    ldm4(sb + 1024 + ASPLIT + off, al[t]);
                }
                uint4 Bq[4];
                {
                    size_t base = (size_t)BOFF +
                        ((size_t)(ks * NF2 + g * 4) * 32 + lane) * 16;
#pragma unroll
                    for (int p = 0; p < 4; p++)
                        Bq[p] = *reinterpret_cast<const uint4*>(smem + base + p * 512);
                }
#pragma unroll
                for (int t = 0; t < 2; t++)
#pragma unroll
                    for (int nf = 0; nf < 8; nf++) {
                        uint32_t b0 = (nf & 1) ? Bq[nf >> 1].z : Bq[nf >> 1].x;
                        uint32_t b1 = (nf & 1) ? Bq[nf >> 1].w : Bq[nf >> 1].y;
                        mma16816(acc[t][nf], ah[t], b0, b1);
                    }
#pragma unroll
                for (int t = 0; t < 2; t++)
#pragma unroll
                    for (int nf = 0; nf < 8; nf++) {
                        uint32_t b0 = (nf & 1) ? Bq[nf >> 1].z : Bq[nf >> 1].x;
                        uint32_t b1 = (nf & 1) ? Bq[nf >> 1].w : Bq[nf >> 1].y;
                        mma16816(acc[t][nf], al[t], b0, b1);
                    }
                {
                    size_t base = (size_t)BOFF + BSPLIT +
                        ((size_t)(ks * NF2 + g * 4) * 32 + lane) * 16;
#pragma unroll
                    for (int p = 0; p < 4; p++)
                        Bq[p] = *reinterpret_cast<const uint4*>(smem + base + p * 512);
                }
#pragma unroll
                for (int t = 0; t < 2; t++)
#pragma unroll
                    for (int nf = 0; nf < 8; nf++) {
                        uint32_t b0 = (nf & 1) ? Bq[nf >> 1].z : Bq[nf >> 1].x;
                        uint32_t b1 = (nf & 1) ? Bq[nf >> 1].w : Bq[nf >> 1].y;
                        mma16816(acc[t][nf], ah[t], b0, b1);
                    }
            }
        }

        // epilogue
#pragma unroll
        for (int t = 0; t < 2; t++) {
            int row0 = tt * MTILE + warpM + t * 16 + (lane >> 2);
#pragma unroll
            for (int nf = 0; nf < 8; nf++) {
                int col = g * 64 + nf * 8 + (lane & 3) * 2;
#pragma unroll
                for (int hh = 0; hh < 2; hh++) {
                    int row = row0 + hh * 8;
                    if (row < n) {
                        float ox = acc[t][nf][hh * 2 + 0] + bs[col];
                        float oy = acc[t][nf][hh * 2 + 1] + bs[col + 1];
                        if (RELU) { ox = fmaxf(ox, 0.f); oy = fmaxf(oy, 0.f); }
                        if (OUT_PLANES) {
                            unsigned short h0, l0, h1, l1;
                            split1(ox, h0, l0); split1(oy, h1, l1);
                            *reinterpret_cast<uint32_t*>(outH + (size_t)row * N_OUT + col) =
                                (uint32_t)h0 | ((uint32_t)h1 << 16);
                            *reinterpret_cast<uint32_t*>(outL + (size_t)row * N_OUT + col) =
                                (uint32_t)l0 | ((uint32_t)l1 << 16);
                        } else {
                            *reinterpret_cast<float2*>(outF + (size_t)row * N_OUT + col) =
                                make_float2(ox, oy);
                        }
                    }
                }
            }
        }
    }
}

// ---------------------------------------------------------------------------
// SIMT decoder (f32x2 FMAs), fp32 z inputs
// ---------------------------------------------------------------------------
__launch_bounds__(512, 1)
__global__ void decoder_kernel(const float* __restrict__ zc, const float* __restrict__ zp,
                               const int* __restrict__ row, const int* __restrict__ col,
                               const float* __restrict__ W1, const float* __restrict__ b1,
                               const float* __restrict__ w2, const float* __restrict__ b2,
                               float* __restrict__ out, int nE) {
    constexpr int NOP = 68;
    constexpr int R = 8;
    extern __shared__ float smemf[];
    float* Ws = smemf;
    float* stage = smemf + 128 * NOP;

    int tid = threadIdx.x;
    for (int i = tid; i < 64 * 128; i += 512) {
        int o = i >> 7, k = i & 127;
        Ws[k * NOP + o] = W1[i];
    }
    __syncthreads();

    const int w = tid >> 5, lane = tid & 31;
    float* Zs = stage + w * (R * 128);

    float2 b1v = __ldg(reinterpret_cast<const float2*>(b1 + lane * 2));
    u64 bofs = pack2(b1v.x, b1v.y);
    float w20 = __ldg(w2 + lane * 2), w21 = __ldg(w2 + lane * 2 + 1);
    float b2v = __ldg(b2);

    for (int base = (blockIdx.x * 16 + w) * R; base < nE; base += gridDim.x * 16 * R) {
#pragma unroll
        for (int r = 0; r < R; r++) {
            int e = base + r;
            float4 v = make_float4(0.f, 0.f, 0.f, 0.f);
            if (e < nE) {
                if (lane < 16) {
                    int ri = __ldg(row + e);
                    v = *reinterpret_cast<const float4*>(zc + (size_t)ri * DOUT + lane * 4);
                } else {
                    int ci = __ldg(col + e);
                    v = *reinterpret_cast<const float4*>(zp + (size_t)ci * DOUT + (lane - 16) * 4);
                }
            }
            *reinterpret_cast<float4*>(Zs + r * 128 + lane * 4) = v;
        }
        __syncwarp();

        u64 acc[R];
#pragma unroll
        for (int r = 0; r < R; r++) acc[r] = bofs;

        for (int k0 = 0; k0 < 128; k0 += 4) {
            float4 z4[R];
#pragma unroll
            for (int r = 0; r < R; r++)
                z4[r] = *reinterpret_cast<const float4*>(Zs + r * 128 + k0);
#pragma unroll
            for (int kk = 0; kk < 4; kk++) {
                u64 wv = *reinterpret_cast<const u64*>(Ws + (k0 + kk) * NOP + lane * 2);
#pragma unroll
                for (int r = 0; r < R; r++) {
                    float z = (kk == 0) ? z4[r].x : (kk == 1) ? z4[r].y : (kk == 2) ? z4[r].z : z4[r].w;
                    u64 zd = dup2(z);
                    fma2(acc[r], zd, wv);
                }
            }
        }

#pragma unroll
        for (int r = 0; r < R; r++) {
            float h0, h1;
            unpack2(acc[r], h0, h1);
            h0 = fmaxf(h0, 0.f); h1 = fmaxf(h1, 0.f);
            float p = h0 * w20 + h1 * w21;
#pragma unroll
            for (int o = 16; o > 0; o >>= 1) p += __shfl_xor_sync(0xffffffff, p, o);
            if (lane == 0 && base + r < nE) out[base + r] = p + b2v;
        }
        __syncwarp();
    }
}

// ---------------------------------------------------------------------------
// Host orchestration
// ---------------------------------------------------------------------------
extern "C" void kernel_launch(void* const* d_in, const int* in_sizes, int n_in,
                              void* d_out, int out_size) {
    const float* x_prod = (const float*)d_in[0];
    const float* x_cust = (const float*)d_in[1];
    const int* pp = (const int*)d_in[2];
    const int* pc = (const int*)d_in[3];
    const int* eli = (const int*)d_in[4];

    bool sig = (in_sizes[6] == HID);
    const float* it_W1l = (const float*)d_in[5];
    const float* it_W1r = (const float*)d_in[sig ? 7 : 6];
    const float* it_b1  = (const float*)d_in[sig ? 6 : 7];
    const float* it_W2l = (const float*)d_in[8];
    const float* it_W2r = (const float*)d_in[sig ? 10 : 9];
    const float* it_b2  = (const float*)d_in[sig ? 9 : 10];
    const float* it_Wlin = (const float*)d_in[11];
    const float* it_blin = (const float*)d_in[12];
    const float* us_W1l = (const float*)d_in[13];
    const float* us_W1r = (const float*)d_in[sig ? 15 : 14];
    const float* us_b1  = (const float*)d_in[sig ? 14 : 15];
    const float* us_W2l = (const float*)d_in[16];
    const float* us_W2r = (const float*)d_in[sig ? 18 : 17];
    const float* us_b2  = (const float*)d_in[sig ? 17 : 18];
    const float* us_W3l = (const float*)d_in[19];
    const float* us_W3r = (const float*)d_in[sig ? 21 : 20];
    const float* us_b3  = (const float*)d_in[sig ? 20 : 21];
    const float* us_Wlin = (const float*)d_in[22];
    const float* us_blin = (const float*)d_in[23];
    const float* de_W1 = (const float*)d_in[24];
    const float* de_b1 = (const float*)d_in[25];
    const float* de_W2 = (const float*)d_in[26];
    const float* de_b2 = (const float*)d_in[27];

#define GETP(var, sym, T) T* var; cudaGetSymbolAddress((void**)&var, sym)
    GETP(xPH, g_xPH, bf16); GETP(xPL, g_xPL, bf16);
    GETP(xCH, g_xCH, bf16); GETP(xCL, g_xCL, bf16);
    GETP(P0H, g_P0H, bf16); GETP(P0L, g_P0L, bf16);
    GETP(P1H, g_P1H, bf16); GETP(P1L, g_P1L, bf16);
    GETP(P2H, g_P2H, bf16); GETP(P2L, g_P2L, bf16);
    GETP(P3H, g_P3H, bf16); GETP(P3L, g_P3L, bf16);
    GETP(C0H, g_C0H, bf16); GETP(C0L, g_C0L, bf16);
    GETP(C1H, g_C1H, bf16); GETP(C1L, g_C1L, bf16);
    GETP(C2H, g_C2H, bf16); GETP(C2L, g_C2L, bf16);
    GETP(zprod, g_zprod, float); GETP(zcust, g_zcust, float);
    GETP(cntP, g_cntP, int); GETP(cntC, g_cntC, int);
    GETP(offP, g_offP, int); GETP(curP, g_curP, int); GETP(csrP, g_csrP, int);
    GETP(offC, g_offC, int); GETP(curC, g_curC, int); GETP(csrC, g_csrC, int);
    GETP(lbP, g_lbP, u64); GETP(lbC, g_lbC, u64);
#undef GETP

    constexpr int SM_DUAL = 1024 + 2 * 256 * 128 + 2 * 16 * 8 * 32 * 16;   // 197632
    constexpr int SM_SNGL = 1024 + 2 * 512 * 128 + 2 * 8 * 4 * 32 * 16;    // 164864
    constexpr int SM_DEC  = (128 * 68 + 16 * 8 * 128) * 4;
    cudaFuncSetAttribute(hmma_gemm<128, 256, true, true, true>,
                         cudaFuncAttributeMaxDynamicSharedMemorySize, SM_DUAL);
    cudaFuncSetAttribute(hmma_gemm<64, 128, false, false, false>,
                         cudaFuncAttributeMaxDynamicSharedMemorySize, SM_SNGL);
    cudaFuncSetAttribute(decoder_kernel,
                         cudaFuncAttributeMaxDynamicSharedMemorySize, SM_DEC);

    const int aggP_grid = (N_PROD * 32 + 255) / 256;
    const int aggC_grid = (N_CUST * 32 + 255) / 256;
    const int nbP = (N_PROD + 1023) / 1024;
    const int nbC = (N_CUST + 1023) / 1024;

    // --- CSR-P (3 launches; zero-invariant maintained by tail kernel) ---
    k_count<<<(E_PP + 255) / 256, 256>>>(pp + E_PP, E_PP, cntP);
    k_scan_lb<<<nbP, 1024>>>(cntP, N_PROD, offP, curP, lbP);
    k_fill<<<(E_PP + 255) / 256, 256>>>(pp, pp + E_PP, E_PP, curP, csrP);

    // launch #3 (ncu capture target): first aggregation
    agg_mean<false><<<aggP_grid, 256>>>(x_prod, nullptr, nullptr, offP, csrP,
                                        P0H, P0L, N_PROD, E_PP);

    // x -> planes
    k_convert_x<<<((N_PROD + N_CUST) * 32 + 255) / 256, 256>>>(x_prod, x_cust);

    // --- CSR-C ---
    k_count<<<(E_PC + 255) / 256, 256>>>(pc + E_PC, E_PC, cntC);
    k_scan_lb<<<nbC, 1024>>>(cntC, N_CUST, offC, curC, lbC);
    k_fill<<<(E_PC + 255) / 256, 256>>>(pc, pc + E_PC, E_PC, curC, csrC);

    // ItemGNN + UserGNN layer 1 (share agg#1 output)
    hmma_gemm<128, 256, true, true, true><<<148, 512, SM_DUAL>>>(
        P0H, P0L, xPH, xPL, it_W1l, it_W1r, it_b1, nullptr, P1H, P1L, N_PROD);
    hmma_gemm<128, 256, true, true, true><<<148, 512, SM_DUAL>>>(
        P0H, P0L, xPH, xPL, us_W1l, us_W1r, us_b1, nullptr, P2H, P2L, N_PROD);
    agg_mean<true><<<aggP_grid, 256>>>(nullptr, P1H, P1L, offP, csrP,
                                       P0H, P0L, N_PROD, E_PP);
    hmma_gemm<128, 256, true, true, true><<<148, 512, SM_DUAL>>>(
        P0H, P0L, P1H, P1L, it_W2l, it_W2r, it_b2, nullptr, P3H, P3L, N_PROD);
    hmma_gemm<64, 128, false, false, false><<<148, 512, SM_SNGL>>>(
        P3H, P3L, nullptr, nullptr, it_Wlin, nullptr, it_blin, zprod, nullptr, nullptr, N_PROD);

    // UserGNN
    agg_mean<false><<<aggC_grid, 256>>>(x_prod, nullptr, nullptr, offC, csrC,
                                        C0H, C0L, N_CUST, E_PC);
    hmma_gemm<128, 256, true, true, true><<<148, 512, SM_DUAL>>>(
        C0H, C0L, xCH, xCL, us_W2l, us_W2r, us_b2, nullptr, C1H, C1L, N_CUST);
    agg_mean<true><<<aggC_grid, 256>>>(nullptr, P2H, P2L, offC, csrC,
                                       C0H, C0L, N_CUST, E_PC);
    hmma_gemm<128, 256, true, true, true><<<148, 512, SM_DUAL>>>(
        C0H, C0L, C1H, C1L, us_W3l, us_W3r, us_b3, nullptr, C2H, C2L, N_CUST);
    hmma_gemm<64, 128, false, false, false><<<148, 512, SM_SNGL>>>(
        C2H, C2L, nullptr, nullptr, us_Wlin, nullptr, us_blin, zcust, nullptr, nullptr, N_CUST);

    // Edge decoder
    decoder_kernel<<<296, 512, SM_DEC>>>(zcust, zprod, eli, eli + E_LB,
                                         de_W1, de_b1, de_W2, de_b2,
                                         (float*)d_out, E_LB);

    // restore zero invariant for next call
    k_tail_zero<<<(N_PROD + 255) / 256, 256>>>();
}